// round 2
// baseline (speedup 1.0000x reference)
#include <cuda_runtime.h>
#include <math.h>

#define BB 32
#define LL 196
#define DD 512
#define HH 512
#define EE 256
#define TT 128
#define VV 512
#define A1 256
#define A2 128
#define GG 2048            // 4*H
#define NH 358
#define HZE (HH + DD + EE) // 1280
#define NPG (A1 + GG)      // 2304
#define PADTOK 0

// ---------------- scratch (no allocation allowed) ----------------
__device__ float g_eseq[BB * TT * EE];
__device__ float g_prea[BB * LL * A1];
__device__ float g_egate[BB * TT * GG];
__device__ float g_h[BB * HH];
__device__ float g_c[BB * HH];
__device__ float g_hpg[BB * NPG];
__device__ float g_scores[BB * LL];
__device__ float g_z[BB * DD];
__device__ float g_hze[BB * TT * HZE];
__device__ float g_x1[BB * TT * NH];
__device__ float g_x2[BB * TT * NH];

// ---------------- init h,c ----------------
__global__ void k_init_hc(const float* __restrict__ h0, const float* __restrict__ c0) {
    int i = blockIdx.x * 256 + threadIdx.x;
    if (i < BB * HH) { g_h[i] = h0[i]; g_c[i] = c0[i]; }
}

// ---------------- embedding gather (shift-right w/ pad) ----------------
__global__ void k_embed(const int* __restrict__ y, const float* __restrict__ embed) {
    int bt = blockIdx.x;                 // b*T + t
    int b = bt / TT, t = bt % TT;
    int tok = (t == 0) ? PADTOK : y[b * TT + (t - 1)];
    float v = embed[tok * EE + threadIdx.x];
    g_eseq[bt * EE + threadIdx.x] = v;
    g_hze[bt * HZE + HH + DD + threadIdx.x] = v;   // e part of hze
}

// ---------------- generic tiled SGEMM: C = act(A*W + bias) ----------------
// A[M,K] lda, W[K,N] ldw, C[M,N] ldc. ACT: 0=none 1=tanh
template <int ACT>
__global__ void k_sgemm(const float* __restrict__ A, int lda,
                        const float* __restrict__ W, int ldw,
                        const float* __restrict__ bias,
                        float* __restrict__ C, int ldc,
                        int M, int N, int K) {
    __shared__ float As[16][65];
    __shared__ float Ws[16][65];
    int tx = threadIdx.x % 16, ty = threadIdx.x / 16;
    int row0 = blockIdx.y * 64;
    int col0 = blockIdx.x * 64;
    float acc[4][4] = {};
    for (int k0 = 0; k0 < K; k0 += 16) {
        for (int i = threadIdx.x; i < 64 * 16; i += 256) {
            int r = i >> 4, kk = i & 15;
            int gr = row0 + r, gk = k0 + kk;
            As[kk][r] = (gr < M && gk < K) ? A[gr * lda + gk] : 0.f;
        }
        for (int i = threadIdx.x; i < 16 * 64; i += 256) {
            int kk = i >> 6, c = i & 63;
            int gk = k0 + kk, gc = col0 + c;
            Ws[kk][c] = (gk < K && gc < N) ? W[gk * ldw + gc] : 0.f;
        }
        __syncthreads();
#pragma unroll
        for (int kk = 0; kk < 16; kk++) {
            float a_[4], w_[4];
#pragma unroll
            for (int i = 0; i < 4; i++) a_[i] = As[kk][ty * 4 + i];
#pragma unroll
            for (int j = 0; j < 4; j++) w_[j] = Ws[kk][tx * 4 + j];
#pragma unroll
            for (int i = 0; i < 4; i++)
#pragma unroll
                for (int j = 0; j < 4; j++) acc[i][j] += a_[i] * w_[j];
        }
        __syncthreads();
    }
#pragma unroll
    for (int i = 0; i < 4; i++) {
        int r = row0 + ty * 4 + i;
        if (r >= M) continue;
#pragma unroll
        for (int j = 0; j < 4; j++) {
            int c = col0 + tx * 4 + j;
            if (c >= N) continue;
            float v = acc[i][j] + (bias ? bias[c] : 0.f);
            if (ACT == 1) v = tanhf(v);
            C[r * ldc + c] = v;
        }
    }
}

// ---------------- per-step K1: h projections (att hidden + lstm hh) ----------------
// hpg[b, 0:256]   = h[b] @ att_w1[D:, :]           (no bias)
// hpg[b, 256:2304]= h[b] @ w_hh + b_hh
__global__ void k_proj(const float* __restrict__ w1h,   // att_w1 + D*A1 (ld A1)
                       const float* __restrict__ whh,   // ld GG
                       const float* __restrict__ bhh) {
    int n = blockIdx.x * 128 + threadIdx.x;  // 0..2303
    int m0 = blockIdx.y * 4;                 // 4 batch rows per block
    __shared__ float hs[4][HH];
    for (int i = threadIdx.x; i < 4 * HH; i += 128)
        hs[i / HH][i % HH] = g_h[(m0 + i / HH) * HH + (i % HH)];
    __syncthreads();
    const float* W; int ld, col; float bias;
    if (n < A1) { W = w1h; ld = A1; col = n; bias = 0.f; }
    else        { W = whh; ld = GG; col = n - A1; bias = bhh[n - A1]; }
    float a0 = bias, a1 = bias, a2 = bias, a3 = bias;
#pragma unroll 4
    for (int k = 0; k < HH; k++) {
        float w = W[k * ld + col];
        a0 += hs[0][k] * w; a1 += hs[1][k] * w;
        a2 += hs[2][k] * w; a3 += hs[3][k] * w;
    }
    g_hpg[(m0 + 0) * NPG + n] = a0;
    g_hpg[(m0 + 1) * NPG + n] = a1;
    g_hpg[(m0 + 2) * NPG + n] = a2;
    g_hpg[(m0 + 3) * NPG + n] = a3;
}

// ---------------- per-step K2: attention scores ----------------
// block = (b, 4 consecutive l). x1 = tanh(pre_a + hproj); x2 = tanh(x1@w2+b2);
// score = x2@w3 + b3
__global__ void k_att(const float* __restrict__ w2, const float* __restrict__ b2,
                      const float* __restrict__ w3, const float* __restrict__ b3) {
    int b = blockIdx.y;
    int l0 = blockIdx.x * 4;
    __shared__ float x1s[4][A1];
    __shared__ float red[4][4];
    int tid = threadIdx.x;
    const float* hp = g_hpg + b * NPG;
    for (int i = tid; i < 4 * A1; i += 128) {
        int li = i / A1, k = i % A1;
        x1s[li][k] = tanhf(g_prea[(b * LL + l0 + li) * A1 + k] + hp[k]);
    }
    __syncthreads();
    float acc0 = b2[tid], acc1 = acc0, acc2 = acc0, acc3 = acc0;
#pragma unroll 8
    for (int k = 0; k < A1; k++) {
        float w = w2[k * A2 + tid];
        acc0 += x1s[0][k] * w; acc1 += x1s[1][k] * w;
        acc2 += x1s[2][k] * w; acc3 += x1s[3][k] * w;
    }
    float w3v = w3[tid];
    float p0 = tanhf(acc0) * w3v, p1 = tanhf(acc1) * w3v;
    float p2 = tanhf(acc2) * w3v, p3 = tanhf(acc3) * w3v;
#pragma unroll
    for (int off = 16; off; off >>= 1) {
        p0 += __shfl_down_sync(0xffffffffu, p0, off);
        p1 += __shfl_down_sync(0xffffffffu, p1, off);
        p2 += __shfl_down_sync(0xffffffffu, p2, off);
        p3 += __shfl_down_sync(0xffffffffu, p3, off);
    }
    int warp = tid >> 5, lane = tid & 31;
    if (lane == 0) { red[0][warp] = p0; red[1][warp] = p1; red[2][warp] = p2; red[3][warp] = p3; }
    __syncthreads();
    if (tid < 4) {
        float s = red[tid][0] + red[tid][1] + red[tid][2] + red[tid][3] + b3[0];
        g_scores[b * LL + l0 + tid] = s;
    }
}

// ---------------- per-step K3: softmax + context z ----------------
__global__ void k_soft_z(const float* __restrict__ a, int t) {
    int b = blockIdx.x;
    __shared__ float al[LL];
    __shared__ float rbuf[8];
    int tid = threadIdx.x, lane = tid & 31, warp = tid >> 5;
    float v = (tid < LL) ? g_scores[b * LL + tid] : -1e30f;
    // max
    float m = v;
#pragma unroll
    for (int off = 16; off; off >>= 1) m = fmaxf(m, __shfl_xor_sync(0xffffffffu, m, off));
    if (lane == 0) rbuf[warp] = m;
    __syncthreads();
    m = rbuf[0];
#pragma unroll
    for (int i = 1; i < 8; i++) m = fmaxf(m, rbuf[i]);
    float e = (tid < LL) ? expf(v - m) : 0.f;
    __syncthreads();
    // sum
    float s = e;
#pragma unroll
    for (int off = 16; off; off >>= 1) s += __shfl_xor_sync(0xffffffffu, s, off);
    if (lane == 0) rbuf[warp] = s;
    __syncthreads();
    s = rbuf[0] + rbuf[1] + rbuf[2] + rbuf[3] + rbuf[4] + rbuf[5] + rbuf[6] + rbuf[7];
    float inv = 1.f / s;
    if (tid < LL) al[tid] = e * inv;
    __syncthreads();
    // z[b,d] = sum_l alpha[l]*a[b,l,d]
    for (int d = tid; d < DD; d += 256) {
        float acc = 0.f;
        const float* ab = a + (size_t)(b * LL) * DD + d;
#pragma unroll 4
        for (int l = 0; l < LL; l++) acc += al[l] * ab[l * DD];
        g_z[b * DD + d] = acc;
        g_hze[(b * TT + t) * HZE + HH + d] = acc;   // z part
    }
}

// ---------------- per-step K4: LSTM gates from z + update ----------------
__global__ void k_lstm(const float* __restrict__ wih, int t) {
    int b = blockIdx.y;
    int jp = blockIdx.x * 128 + threadIdx.x;     // hidden index 0..511
    __shared__ float zs[DD];
    for (int i = threadIdx.x; i < DD; i += 128) zs[i] = g_z[b * DD + i];
    __syncthreads();
    const float* eg = g_egate + (size_t)(b * TT + t) * GG;  // e@w_ih[D:] + b_ih
    const float* hg = g_hpg + b * NPG + A1;                 // h@w_hh + b_hh
    float ai = eg[jp] + hg[jp];
    float af = eg[jp + 512] + hg[jp + 512];
    float ag = eg[jp + 1024] + hg[jp + 1024];
    float ao = eg[jp + 1536] + hg[jp + 1536];
#pragma unroll 4
    for (int d = 0; d < DD; d++) {
        float zv = zs[d];
        const float* wr = wih + d * GG + jp;
        ai += zv * wr[0];
        af += zv * wr[512];
        ag += zv * wr[1024];
        ao += zv * wr[1536];
    }
    float i_ = 1.f / (1.f + expf(-ai));
    float f_ = 1.f / (1.f + expf(-af));
    float o_ = 1.f / (1.f + expf(-ao));
    float gv = tanhf(ag);
    float c = f_ * g_c[b * HH + jp] + i_ * gv;
    float h = o_ * tanhf(c);
    g_c[b * HH + jp] = c;
    g_h[b * HH + jp] = h;
    g_hze[(b * TT + t) * HZE + jp] = h;             // h part
}

// ---------------- launch ----------------
extern "C" void kernel_launch(void* const* d_in, const int* in_sizes, int n_in,
                              void* d_out, int out_size) {
    const float* a      = (const float*)d_in[0];
    const float* h0     = (const float*)d_in[1];
    const float* c0     = (const float*)d_in[2];
    const int*   y      = (const int*)d_in[3];
    const float* att_w1 = (const float*)d_in[4];
    const float* att_b1 = (const float*)d_in[5];
    const float* att_w2 = (const float*)d_in[6];
    const float* att_b2 = (const float*)d_in[7];
    const float* att_w3 = (const float*)d_in[8];
    const float* att_b3 = (const float*)d_in[9];
    const float* w_ih   = (const float*)d_in[10];
    const float* w_hh   = (const float*)d_in[11];
    const float* b_ih   = (const float*)d_in[12];
    const float* b_hh   = (const float*)d_in[13];
    const float* embed  = (const float*)d_in[14];
    const float* out_w1 = (const float*)d_in[15];
    const float* out_b1 = (const float*)d_in[16];
    const float* out_w2 = (const float*)d_in[17];
    const float* out_b2 = (const float*)d_in[18];
    const float* out_w3 = (const float*)d_in[19];
    const float* out_b3 = (const float*)d_in[20];
    float* out = (float*)d_out;

    float *prea, *eseq, *egate, *hze, *x1, *x2;
    cudaGetSymbolAddress((void**)&prea,  g_prea);
    cudaGetSymbolAddress((void**)&eseq,  g_eseq);
    cudaGetSymbolAddress((void**)&egate, g_egate);
    cudaGetSymbolAddress((void**)&hze,   g_hze);
    cudaGetSymbolAddress((void**)&x1,    g_x1);
    cudaGetSymbolAddress((void**)&x2,    g_x2);

    k_init_hc<<<(BB * HH + 255) / 256, 256>>>(h0, c0);
    k_embed<<<BB * TT, EE>>>(y, embed);

    // pre_a[B*L,256] = a @ att_w1[:D] + b1
    k_sgemm<0><<<dim3((A1 + 63) / 64, (BB * LL + 63) / 64), 256>>>(
        a, DD, att_w1, A1, att_b1, prea, A1, BB * LL, A1, DD);
    // e_gates[B*T,2048] = e_seq @ w_ih[D:] + b_ih
    k_sgemm<0><<<dim3((GG + 63) / 64, (BB * TT + 63) / 64), 256>>>(
        eseq, EE, w_ih + (size_t)DD * GG, GG, b_ih, egate, GG, BB * TT, GG, EE);

    for (int t = 0; t < TT; t++) {
        k_proj<<<dim3(NPG / 128, BB / 4), 128>>>(att_w1 + (size_t)DD * A1, w_hh, b_hh);
        k_att<<<dim3(LL / 4, BB), 128>>>(att_w2, att_b2, att_w3, att_b3);
        k_soft_z<<<BB, 256>>>(a, t);
        k_lstm<<<dim3(HH / 128, BB), 128>>>(w_ih, t);
    }

    // output MLP: (B*T,1280) -> 358 tanh -> 358 tanh -> V
    k_sgemm<1><<<dim3((NH + 63) / 64, (BB * TT + 63) / 64), 256>>>(
        hze, HZE, out_w1, NH, out_b1, x1, NH, BB * TT, NH, HZE);
    k_sgemm<1><<<dim3((NH + 63) / 64, (BB * TT + 63) / 64), 256>>>(
        x1, NH, out_w2, NH, out_b2, x2, NH, BB * TT, NH, NH);
    k_sgemm<0><<<dim3((VV + 63) / 64, (BB * TT + 63) / 64), 256>>>(
        x2, NH, out_w3, VV, out_b3, out, VV, BB * TT, VV, NH);
}